// round 1
// baseline (speedup 1.0000x reference)
#include <cuda_runtime.h>

#define BATCH 2
#define SEQ 2048
#define DMODEL 768
#define NH 12
#define DKH 64
#define MROWS (BATCH*SEQ)

// scratch (no allocs allowed)
__device__ float g_qp[BATCH*NH*SEQ*DKH];
__device__ float g_kp[BATCH*NH*SEQ*DKH];
__device__ float g_vp[BATCH*NH*SEQ*DKH];
__device__ float g_ctx[MROWS*DMODEL];

#define AS_STRIDE 20   // 16 + 4 pad (floats), keeps float4 alignment, breaks bank patterns

// Y(64x64 tile) = X[.,768] @ W[.,768]^T  ; both operands K-major rows.
// Thread (ty,tx) owns rows {ty+16i}, cols {tx+16j}.
__device__ __forceinline__ void gemm_tile(const float* __restrict__ X,
                                          const float* __restrict__ W,
                                          int bm, int bn, float acc[4][4],
                                          float* As, float* Bs)
{
    const int t  = threadIdx.x;
    const int tx = t & 15, ty = t >> 4;
    const int lr = t >> 2;          // 0..63
    const int lc = (t & 3) * 4;     // 0,4,8,12
    const float* xp = X + (size_t)(bm + lr) * DMODEL + lc;
    const float* wp = W + (size_t)(bn + lr) * DMODEL + lc;

    for (int k0 = 0; k0 < DMODEL; k0 += 16) {
        float4 a = *(const float4*)(xp + k0);
        float4 b = *(const float4*)(wp + k0);
        *(float4*)(As + lr*AS_STRIDE + lc) = a;
        *(float4*)(Bs + lr*AS_STRIDE + lc) = b;
        __syncthreads();
        #pragma unroll
        for (int kc = 0; kc < 4; kc++) {
            float4 av[4], bv[4];
            #pragma unroll
            for (int i = 0; i < 4; i++)
                av[i] = *(const float4*)(As + (ty + 16*i)*AS_STRIDE + kc*4);
            #pragma unroll
            for (int j = 0; j < 4; j++)
                bv[j] = *(const float4*)(Bs + (tx + 16*j)*AS_STRIDE + kc*4);
            #pragma unroll
            for (int i = 0; i < 4; i++)
                #pragma unroll
                for (int j = 0; j < 4; j++) {
                    acc[i][j] += av[i].x*bv[j].x;
                    acc[i][j] += av[i].y*bv[j].y;
                    acc[i][j] += av[i].z*bv[j].z;
                    acc[i][j] += av[i].w*bv[j].w;
                }
        }
        __syncthreads();
    }
}

__global__ __launch_bounds__(256) void qkv_proj_kernel(
    const float* __restrict__ q, const float* __restrict__ k, const float* __restrict__ v,
    const float* __restrict__ wq, const float* __restrict__ wk, const float* __restrict__ wv,
    const float* __restrict__ bq, const float* __restrict__ bk, const float* __restrict__ bv)
{
    __shared__ float As[64*AS_STRIDE];
    __shared__ float Bs[64*AS_STRIDE];

    const float* X; const float* W; const float* bias; float* Y;
    if (blockIdx.z == 0)      { X = q; W = wq; bias = bq; Y = g_qp; }
    else if (blockIdx.z == 1) { X = k; W = wk; bias = bk; Y = g_kp; }
    else                      { X = v; W = wv; bias = bv; Y = g_vp; }

    const int bm = blockIdx.y * 64;
    const int bn = blockIdx.x * 64;   // 64-wide == exactly one head
    float acc[4][4] = {};
    gemm_tile(X, W, bm, bn, acc, As, Bs);

    const int t = threadIdx.x;
    const int tx = t & 15, ty = t >> 4;
    const int h = bn >> 6;
    #pragma unroll
    for (int i = 0; i < 4; i++) {
        const int m  = bm + ty + 16*i;
        const int b_ = m >> 11;
        const int s_ = m & (SEQ - 1);
        float* yrow = Y + (size_t)((b_*NH + h)*SEQ + s_) * DKH;
        #pragma unroll
        for (int j = 0; j < 4; j++) {
            const int n = bn + tx + 16*j;
            yrow[n & 63] = acc[i][j] + bias[n];
        }
    }
}

__global__ __launch_bounds__(256) void out_proj_kernel(
    const float* __restrict__ wo, const float* __restrict__ bo, float* __restrict__ out)
{
    __shared__ float As[64*AS_STRIDE];
    __shared__ float Bs[64*AS_STRIDE];

    const int bm = blockIdx.y * 64;
    const int bn = blockIdx.x * 64;
    float acc[4][4] = {};
    gemm_tile(g_ctx, wo, bm, bn, acc, As, Bs);

    const int t = threadIdx.x;
    const int tx = t & 15, ty = t >> 4;
    #pragma unroll
    for (int i = 0; i < 4; i++) {
        const int m = bm + ty + 16*i;
        #pragma unroll
        for (int j = 0; j < 4; j++) {
            const int n = bn + tx + 16*j;
            out[(size_t)m*DMODEL + n] = acc[i][j] + bo[n];
        }
    }
}

#define TS 68  // padded tile row stride (floats)
#define ATTN_SMEM (4*64*TS*4)

__global__ __launch_bounds__(256) void attn_kernel(const int* __restrict__ mask)
{
    extern __shared__ float sm[];
    float* Qs = sm;                 // [q][d]  natural
    float* Ks = sm + 64*TS;         // [k][d]  natural
    float* Vt = sm + 2*64*TS;       // [d][k]  transposed
    float* Ps = sm + 3*64*TS;       // [q][k]  natural

    const int t  = threadIdx.x;
    const int tx = t & 15, ty = t >> 4;
    const int q0 = blockIdx.x * 64;
    const int h  = blockIdx.y;
    const int b_ = blockIdx.z;

    const float* Q = g_qp + (size_t)((b_*NH + h)*SEQ) * DKH;
    const float* K = g_kp + (size_t)((b_*NH + h)*SEQ) * DKH;
    const float* V = g_vp + (size_t)((b_*NH + h)*SEQ) * DKH;

    // load Q tile (once)
    #pragma unroll
    for (int r = 0; r < 4; r++) {
        int idx = t + 256*r;
        int row = idx >> 4, c4 = (idx & 15) * 4;
        *(float4*)(Qs + row*TS + c4) = *(const float4*)(Q + (size_t)(q0+row)*DKH + c4);
    }

    float acc[4][4] = {};
    float mrun[4], lrun[4];
    #pragma unroll
    for (int i = 0; i < 4; i++) { mrun[i] = -1e30f; lrun[i] = 0.0f; }

    for (int k0 = 0; k0 < SEQ; k0 += 64) {
        __syncthreads();   // prev PV done; Qs visible on first iter

        // K tile natural layout
        #pragma unroll
        for (int r = 0; r < 4; r++) {
            int idx = t + 256*r;
            int row = idx >> 4, c4 = (idx & 15) * 4;
            *(float4*)(Ks + row*TS + c4) = *(const float4*)(K + (size_t)(k0+row)*DKH + c4);
        }
        // V tile: 4x4 register transpose -> Vt[d][k]
        {
            const int kb = (t >> 4) * 4;   // coalesced gmem reads across tx
            const int db = (t & 15) * 4;
            const float* vb = V + (size_t)(k0 + kb)*DKH + db;
            float4 r0 = *(const float4*)(vb);
            float4 r1 = *(const float4*)(vb + DKH);
            float4 r2 = *(const float4*)(vb + 2*DKH);
            float4 r3 = *(const float4*)(vb + 3*DKH);
            *(float4*)(Vt + (db+0)*TS + kb) = make_float4(r0.x, r1.x, r2.x, r3.x);
            *(float4*)(Vt + (db+1)*TS + kb) = make_float4(r0.y, r1.y, r2.y, r3.y);
            *(float4*)(Vt + (db+2)*TS + kb) = make_float4(r0.z, r1.z, r2.z, r3.z);
            *(float4*)(Vt + (db+3)*TS + kb) = make_float4(r0.w, r1.w, r2.w, r3.w);
        }
        __syncthreads();

        // S = Q K^T (dot over d)
        float s[4][4] = {};
        #pragma unroll
        for (int kc = 0; kc < 16; kc++) {
            float4 qv[4], kv[4];
            #pragma unroll
            for (int i = 0; i < 4; i++) qv[i] = *(const float4*)(Qs + (ty+16*i)*TS + kc*4);
            #pragma unroll
            for (int j = 0; j < 4; j++) kv[j] = *(const float4*)(Ks + (tx+16*j)*TS + kc*4);
            #pragma unroll
            for (int i = 0; i < 4; i++)
                #pragma unroll
                for (int j = 0; j < 4; j++) {
                    s[i][j] += qv[i].x*kv[j].x; s[i][j] += qv[i].y*kv[j].y;
                    s[i][j] += qv[i].z*kv[j].z; s[i][j] += qv[i].w*kv[j].w;
                }
        }

        // mask + online softmax (row stats across the 16 tx lanes)
        #pragma unroll
        for (int i = 0; i < 4; i++) {
            const int* mrow = mask + (size_t)(q0 + ty + 16*i) * SEQ + k0;
            float sv[4];
            #pragma unroll
            for (int j = 0; j < 4; j++) {
                int mk = mrow[tx + 16*j];
                sv[j] = mk ? s[i][j] * 0.125f : -1e9f;   // scale then mask, like reference
            }
            float mx = fmaxf(fmaxf(sv[0], sv[1]), fmaxf(sv[2], sv[3]));
            mx = fmaxf(mx, __shfl_xor_sync(0xffffffffu, mx, 1));
            mx = fmaxf(mx, __shfl_xor_sync(0xffffffffu, mx, 2));
            mx = fmaxf(mx, __shfl_xor_sync(0xffffffffu, mx, 4));
            mx = fmaxf(mx, __shfl_xor_sync(0xffffffffu, mx, 8));
            float mnew  = fmaxf(mrun[i], mx);
            float alpha = __expf(mrun[i] - mnew);
            float rs = 0.0f;
            #pragma unroll
            for (int j = 0; j < 4; j++) {
                float p = __expf(sv[j] - mnew);
                Ps[(ty+16*i)*TS + tx + 16*j] = p;
                rs += p;
            }
            rs += __shfl_xor_sync(0xffffffffu, rs, 1);
            rs += __shfl_xor_sync(0xffffffffu, rs, 2);
            rs += __shfl_xor_sync(0xffffffffu, rs, 4);
            rs += __shfl_xor_sync(0xffffffffu, rs, 8);
            lrun[i] = lrun[i]*alpha + rs;
            mrun[i] = mnew;
            #pragma unroll
            for (int j = 0; j < 4; j++) acc[i][j] *= alpha;
        }
        __syncthreads();

        // O += P @ V   (dot over k; Vt is [d][k])
        #pragma unroll
        for (int kc = 0; kc < 16; kc++) {
            float4 pv[4], vv[4];
            #pragma unroll
            for (int i = 0; i < 4; i++) pv[i] = *(const float4*)(Ps + (ty+16*i)*TS + kc*4);
            #pragma unroll
            for (int j = 0; j < 4; j++) vv[j] = *(const float4*)(Vt + (tx+16*j)*TS + kc*4);
            #pragma unroll
            for (int i = 0; i < 4; i++)
                #pragma unroll
                for (int j = 0; j < 4; j++) {
                    acc[i][j] += pv[i].x*vv[j].x; acc[i][j] += pv[i].y*vv[j].y;
                    acc[i][j] += pv[i].z*vv[j].z; acc[i][j] += pv[i].w*vv[j].w;
                }
        }
    }

    // normalize + write context in [B,S,H*Dk] layout for the output GEMM
    #pragma unroll
    for (int i = 0; i < 4; i++) {
        float inv = 1.0f / lrun[i];
        int srow = q0 + ty + 16*i;
        float* crow = g_ctx + (size_t)(b_*SEQ + srow)*DMODEL + h*DKH;
        #pragma unroll
        for (int j = 0; j < 4; j++)
            crow[tx + 16*j] = acc[i][j] * inv;
    }
}

extern "C" void kernel_launch(void* const* d_in, const int* in_sizes, int n_in,
                              void* d_out, int out_size)
{
    const float* q   = (const float*)d_in[0];
    const float* k   = (const float*)d_in[1];
    const float* v   = (const float*)d_in[2];
    const int*   msk = (const int*)  d_in[3];
    const float* w_q = (const float*)d_in[4];
    const float* b_q = (const float*)d_in[5];
    const float* w_k = (const float*)d_in[6];
    const float* b_k = (const float*)d_in[7];
    const float* w_v = (const float*)d_in[8];
    const float* b_v = (const float*)d_in[9];
    const float* w_o = (const float*)d_in[10];
    const float* b_o = (const float*)d_in[11];
    float* out = (float*)d_out;

    cudaFuncSetAttribute(attn_kernel, cudaFuncAttributeMaxDynamicSharedMemorySize, ATTN_SMEM);

    qkv_proj_kernel<<<dim3(DMODEL/64, MROWS/64, 3), 256>>>(q, k, v, w_q, w_k, w_v, b_q, b_k, b_v);
    attn_kernel<<<dim3(SEQ/64, NH, BATCH), 256, ATTN_SMEM>>>(msk);
    out_proj_kernel<<<dim3(DMODEL/64, MROWS/64, 1), 256>>>(w_o, b_o, out);
}